// round 6
// baseline (speedup 1.0000x reference)
#include <cuda_runtime.h>
#include <cuda_fp16.h>
#include <cstdint>

// RNN-T Joiner: fused fp16 tensor-core GEMM, tanh inline (no A scratch).
// out[m, v] = tanh(src[b,t,:] + tgt[b,u,:]) . W[v,:] + bias[v]
// M = 160000, K = 512, N = 1024.
// CTA 128x128, BK=32, 8 warps (2m x 4n, 64x32 warp tiles), mma m16n8k16
// f32.f16.f16.f32, ldmatrix fragment loads, 4-stage cp.async for W(fp16),
// register-prefetch + MUFU tanh + STS for A.

constexpr int Bb = 4, Tt = 400, Uu = 100, Dd = 512, Vv = 1024;
constexpr long long Mm = (long long)Bb * Tt * Uu;   // 160000 = 128*1250

#define BM 128
#define BN 128
#define BK 32
#define NCH (Dd / BK)      // 16
#define BSTG 4             // W cp.async stages
#define RST 40             // smem row stride in halfs (80B) - conflict-free

__device__ __half W_half[(size_t)Vv * Dd];   // 1 MB scratch (sanctioned)

__device__ __forceinline__ float fast_tanh(float x) {
    float y; asm("tanh.approx.f32 %0, %1;" : "=f"(y) : "f"(x)); return y;
}
__device__ __forceinline__ uint32_t smem_u32(const void* p) {
    uint32_t a;
    asm("{ .reg .u64 t; cvta.to.shared.u64 t, %1; cvt.u32.u64 %0, t; }" : "=r"(a) : "l"(p));
    return a;
}
__device__ __forceinline__ void mma_fp16(float* d, const uint32_t* a,
                                         uint32_t b0, uint32_t b1) {
    asm volatile(
        "mma.sync.aligned.m16n8k16.row.col.f32.f16.f16.f32 "
        "{%0,%1,%2,%3}, {%4,%5,%6,%7}, {%8,%9}, {%0,%1,%2,%3};"
        : "+f"(d[0]), "+f"(d[1]), "+f"(d[2]), "+f"(d[3])
        : "r"(a[0]), "r"(a[1]), "r"(a[2]), "r"(a[3]), "r"(b0), "r"(b1));
}
__device__ __forceinline__ void ldm_x4(uint32_t* r, uint32_t addr) {
    asm volatile("ldmatrix.sync.aligned.m8n8.x4.shared.b16 {%0,%1,%2,%3}, [%4];"
                 : "=r"(r[0]), "=r"(r[1]), "=r"(r[2]), "=r"(r[3]) : "r"(addr));
}

// ---------------- prep: W -> fp16 (one-time, 1 MB) ----------------
__global__ __launch_bounds__(256)
void prep_w_kernel(const float* __restrict__ W) {
    size_t idx = ((size_t)blockIdx.x * 256 + threadIdx.x) * 8;
    float4 w0 = *reinterpret_cast<const float4*>(W + idx);
    float4 w1 = *reinterpret_cast<const float4*>(W + idx + 4);
    __half2 h[4];
    h[0] = __floats2half2_rn(w0.x, w0.y);
    h[1] = __floats2half2_rn(w0.z, w0.w);
    h[2] = __floats2half2_rn(w1.x, w1.y);
    h[3] = __floats2half2_rn(w1.z, w1.w);
    *reinterpret_cast<uint4*>(&W_half[idx]) = *reinterpret_cast<uint4*>(h);
}

constexpr int A_STG_H = BM * RST;                // 5120 halfs / stage
constexpr int B_STG_H = BN * RST;
constexpr int SMEM_TOTAL = (2 * A_STG_H + BSTG * B_STG_H) * 2;  // 61440 B

__global__ __launch_bounds__(256, 2)
void joiner_gemm_fused(const float* __restrict__ src, const float* __restrict__ tgt,
                       const float* __restrict__ bias, float* __restrict__ out) {
    extern __shared__ __half sm[];
    __half* Asm = sm;                       // 2 stages
    __half* Bsm = sm + 2 * A_STG_H;         // BSTG stages

    const int tid = threadIdx.x;
    const int wid = tid >> 5, lid = tid & 31;
    const int g = lid >> 2, c = lid & 3;
    const int wm = wid >> 2, wn = wid & 3;
    const size_t m0 = (size_t)blockIdx.x * BM;
    const int n0 = blockIdx.y * BN;

    // producer mapping: row r = tid/2, k-half h = tid&1 (16 halfs each)
    const int r = tid >> 1;
    const int h = tid & 1;

    const float* sp;
    const float* tp;
    {
        long long m = (long long)m0 + r;
        int b = (int)(m / (Tt * Uu));
        int rem = (int)(m - (long long)b * (Tt * Uu));
        int t = rem / Uu;
        int u = rem - t * Uu;
        sp = src + ((size_t)b * Tt + t) * Dd + h * 16;
        tp = tgt + ((size_t)b * Uu + u) * Dd + h * 16;
    }
    const __half* wgp = W_half + (size_t)(n0 + r) * Dd + h * 16;
    const uint32_t a_base = smem_u32(Asm);
    const uint32_t b_dst0 = smem_u32(Bsm) + (uint32_t)(r * (RST * 2) + h * 32);

    // ldmatrix source addresses (per-lane)
    // A: lanes 0-15 -> rows m..m+15 @ kb; lanes 16-31 -> same rows @ kb+8
    const uint32_t a_lm = a_base + (uint32_t)((wm * 64 + (lid & 15)) * (RST * 2)
                                              + ((lid >> 4) & 1) * 16);
    // B: quad q=lid>>3: row n + (q>>1)*8 + (lid&7), k = kb + (q&1)*8
    const uint32_t b_lm = smem_u32(Bsm)
        + (uint32_t)((wn * 32 + ((lid >> 4) & 1) * 8 + (lid & 7)) * (RST * 2)
                     + ((lid >> 3) & 1) * 16);

    float acc[4][4][4];
#pragma unroll
    for (int mt = 0; mt < 4; mt++)
#pragma unroll
        for (int nt = 0; nt < 4; nt++)
#pragma unroll
            for (int i = 0; i < 4; i++) acc[mt][nt][i] = 0.0f;

#define ISSUE_B(CH) do {                                                        \
        uint32_t bd_ = b_dst0 + ((CH) & (BSTG - 1)) * (B_STG_H * 2);            \
        const __half* bg_ = wgp + (CH) * BK;                                    \
        asm volatile(                                                           \
            "cp.async.cg.shared.global [%0], [%1], 16;\n"                       \
            "cp.async.cg.shared.global [%2], [%3], 16;\n"                       \
            "cp.async.commit_group;"                                            \
            :: "r"(bd_), "l"(bg_), "r"(bd_ + 16), "l"(bg_ + 8) : "memory");     \
    } while (0)

    ISSUE_B(0); ISSUE_B(1); ISSUE_B(2);

    // prefetch A chunk 0 operands
    float4 as0 = *reinterpret_cast<const float4*>(sp);
    float4 as1 = *reinterpret_cast<const float4*>(sp + 4);
    float4 at0 = *reinterpret_cast<const float4*>(tp);
    float4 at1 = *reinterpret_cast<const float4*>(tp + 4);
    float4 as2 = *reinterpret_cast<const float4*>(sp + 8);
    float4 as3 = *reinterpret_cast<const float4*>(sp + 12);
    float4 at2 = *reinterpret_cast<const float4*>(tp + 8);
    float4 at3 = *reinterpret_cast<const float4*>(tp + 12);

    for (int ch = 0; ch < NCH; ch++) {
        const int s = ch & 1;

        // ---- STS A(ch): tanh + fp16 pack, 16 halfs ----
        {
            __half2 hv[8];
            hv[0] = __floats2half2_rn(fast_tanh(as0.x + at0.x), fast_tanh(as0.y + at0.y));
            hv[1] = __floats2half2_rn(fast_tanh(as0.z + at0.z), fast_tanh(as0.w + at0.w));
            hv[2] = __floats2half2_rn(fast_tanh(as1.x + at1.x), fast_tanh(as1.y + at1.y));
            hv[3] = __floats2half2_rn(fast_tanh(as1.z + at1.z), fast_tanh(as1.w + at1.w));
            hv[4] = __floats2half2_rn(fast_tanh(as2.x + at2.x), fast_tanh(as2.y + at2.y));
            hv[5] = __floats2half2_rn(fast_tanh(as2.z + at2.z), fast_tanh(as2.w + at2.w));
            hv[6] = __floats2half2_rn(fast_tanh(as3.x + at3.x), fast_tanh(as3.y + at3.y));
            hv[7] = __floats2half2_rn(fast_tanh(as3.z + at3.z), fast_tanh(as3.w + at3.w));
            __half* adst = Asm + s * A_STG_H + r * RST + h * 16;
            *reinterpret_cast<uint4*>(adst) = *reinterpret_cast<uint4*>(&hv[0]);
            *reinterpret_cast<uint4*>(adst + 8) = *reinterpret_cast<uint4*>(&hv[4]);
        }

        // ---- prefetch A(ch+1) ----
        if (ch + 1 < NCH) {
            const int k0n = (ch + 1) * BK;
            as0 = *reinterpret_cast<const float4*>(sp + k0n);
            as1 = *reinterpret_cast<const float4*>(sp + k0n + 4);
            at0 = *reinterpret_cast<const float4*>(tp + k0n);
            at1 = *reinterpret_cast<const float4*>(tp + k0n + 4);
            as2 = *reinterpret_cast<const float4*>(sp + k0n + 8);
            as3 = *reinterpret_cast<const float4*>(sp + k0n + 12);
            at2 = *reinterpret_cast<const float4*>(tp + k0n + 8);
            at3 = *reinterpret_cast<const float4*>(tp + k0n + 12);
        }

        const int rem = NCH - 1 - ch;
        if (rem >= 2)      asm volatile("cp.async.wait_group 2;" ::: "memory");
        else if (rem == 1) asm volatile("cp.async.wait_group 1;" ::: "memory");
        else               asm volatile("cp.async.wait_group 0;" ::: "memory");
        __syncthreads();
        if (ch + 3 < NCH) ISSUE_B(ch + 3);

        const uint32_t a_st = a_lm + s * (A_STG_H * 2);
        const uint32_t b_st = b_lm + (ch & (BSTG - 1)) * (B_STG_H * 2);
#pragma unroll
        for (int ks = 0; ks < 2; ks++) {
            const int kbB = ks * 32;   // bytes: 16 halfs
            uint32_t a[4][4];
#pragma unroll
            for (int mt = 0; mt < 4; mt++)
                ldm_x4(a[mt], a_st + mt * 16 * (RST * 2) + kbB);
            uint32_t b[2][4];
            ldm_x4(b[0], b_st + kbB);                       // nt 0,1
            ldm_x4(b[1], b_st + 16 * (RST * 2) + kbB);      // nt 2,3
#pragma unroll
            for (int nt = 0; nt < 4; nt++) {
                uint32_t b0 = b[nt >> 1][(nt & 1) * 2];
                uint32_t b1 = b[nt >> 1][(nt & 1) * 2 + 1];
#pragma unroll
                for (int mt = 0; mt < 4; mt++)
                    mma_fp16(acc[mt][nt], a[mt], b0, b1);
            }
        }
    }

    // ---- epilogue: bias + float2 stores ----
#pragma unroll
    for (int nt = 0; nt < 4; nt++) {
        const int col = n0 + wn * 32 + nt * 8 + 2 * c;
        const float2 bz = *reinterpret_cast<const float2*>(bias + col);
#pragma unroll
        for (int mt = 0; mt < 4; mt++) {
            const size_t row = m0 + wm * 64 + mt * 16 + g;
            float2 o1, o2;
            o1.x = acc[mt][nt][0] + bz.x;
            o1.y = acc[mt][nt][1] + bz.y;
            o2.x = acc[mt][nt][2] + bz.x;
            o2.y = acc[mt][nt][3] + bz.y;
            *reinterpret_cast<float2*>(out + row * Vv + col) = o1;
            *reinterpret_cast<float2*>(out + (row + 8) * Vv + col) = o2;
        }
    }
}

// Defensive tail: append lengths if harness packs the whole tuple.
__global__ void joiner_tail_kernel(const int* __restrict__ src_len,
                                   const int* __restrict__ tgt_len,
                                   float* __restrict__ out, int extras) {
    int i = threadIdx.x;
    if (i < extras) {
        size_t base = (size_t)Mm * Vv;
        if (i < Bb) out[base + i] = (float)src_len[i];
        else if (i < 2 * Bb) out[base + i] = (float)tgt_len[i - Bb];
        else out[base + i] = 0.0f;
    }
}

extern "C" void kernel_launch(void* const* d_in, const int* in_sizes, int n_in,
                              void* d_out, int out_size) {
    const float* src     = (const float*)d_in[0];
    const int*   src_len = (const int*)d_in[1];
    const float* tgt     = (const float*)d_in[2];
    const int*   tgt_len = (const int*)d_in[3];
    const float* W       = (const float*)d_in[4];
    const float* bias    = (const float*)d_in[5];
    float* out = (float*)d_out;

    prep_w_kernel<<<(Vv * Dd / 8) / 256, 256>>>(W);

    cudaFuncSetAttribute(joiner_gemm_fused,
                         cudaFuncAttributeMaxDynamicSharedMemorySize, SMEM_TOTAL);
    dim3 grid((unsigned)(Mm / BM), Vv / BN);   // 1250 x 8
    joiner_gemm_fused<<<grid, 256, SMEM_TOTAL>>>(src, tgt, bias, out);

    long long extras = (long long)out_size - (long long)Mm * Vv;
    if (extras > 0) {
        int e = (int)(extras > 64 ? 64 : extras);
        joiner_tail_kernel<<<1, 64>>>(src_len, tgt_len, out, e);
    }
}

// round 7
// speedup vs baseline: 1.5423x; 1.5423x over previous
#include <cuda_runtime.h>
#include <cuda_fp16.h>
#include <cstdint>

// RNN-T Joiner, fp16 tensor-core path, 3-kernel structure (R5) + ldmatrix +
// L2-friendly grid order.
//   prep_a: A_half[m,k] = fp16(tanh(src+tgt))     (164 MB scratch)
//   prep_w: W -> fp16                              (1 MB scratch)
//   gemm:   C = A_half @ W_half^T + bias, mma.sync m16n8k16 f32 accum,
//           4-stage cp.async, ldmatrix.x4 fragment loads.
// M = 160000, K = 512, N = 1024.

constexpr int Bb = 4, Tt = 400, Uu = 100, Dd = 512, Vv = 1024;
constexpr long long Mm = (long long)Bb * Tt * Uu;   // 160000 = 128*1250

#define BM 128
#define BN 128
#define BK 32
#define NCH (Dd / BK)        // 16
#define STG 4                // cp.async stages
#define RST 40               // smem row stride in halfs (80B): conflict-free

__device__ __half A_half[(size_t)Mm * Dd];   // 164 MB scratch (sanctioned)
__device__ __half W_half[(size_t)Vv * Dd];   // 1 MB

__device__ __forceinline__ float fast_tanh(float x) {
    float y; asm("tanh.approx.f32 %0, %1;" : "=f"(y) : "f"(x)); return y;
}
__device__ __forceinline__ uint32_t smem_u32(const void* p) {
    uint32_t a;
    asm("{ .reg .u64 t; cvta.to.shared.u64 t, %1; cvt.u32.u64 %0, t; }" : "=r"(a) : "l"(p));
    return a;
}
__device__ __forceinline__ void mma_fp16(float* d, const uint32_t* a,
                                         uint32_t b0, uint32_t b1) {
    asm volatile(
        "mma.sync.aligned.m16n8k16.row.col.f32.f16.f16.f32 "
        "{%0,%1,%2,%3}, {%4,%5,%6,%7}, {%8,%9}, {%0,%1,%2,%3};"
        : "+f"(d[0]), "+f"(d[1]), "+f"(d[2]), "+f"(d[3])
        : "r"(a[0]), "r"(a[1]), "r"(a[2]), "r"(a[3]), "r"(b0), "r"(b1));
}
__device__ __forceinline__ void ldm_x4(uint32_t* r, uint32_t addr) {
    asm volatile("ldmatrix.sync.aligned.m8n8.x4.shared.b16 {%0,%1,%2,%3}, [%4];"
                 : "=r"(r[0]), "=r"(r[1]), "=r"(r[2]), "=r"(r[3]) : "r"(addr));
}

// ---------------- Phase 1a: A = fp16(tanh(src + tgt)) ----------------
__global__ __launch_bounds__(256)
void prep_a_kernel(const float* __restrict__ src, const float* __restrict__ tgt) {
    size_t idx = (size_t)blockIdx.x * 256 + threadIdx.x;   // one per 8 elems
    int m = (int)(idx >> 6);
    int kv = ((int)idx & 63) * 8;
    int b = m / (Tt * Uu);
    int rem = m - b * (Tt * Uu);
    int t = rem / Uu;
    int u = rem - t * Uu;
    const float* sp = src + ((size_t)b * Tt + t) * Dd + kv;
    const float* tp = tgt + ((size_t)b * Uu + u) * Dd + kv;
    float4 s0 = *reinterpret_cast<const float4*>(sp);
    float4 s1 = *reinterpret_cast<const float4*>(sp + 4);
    float4 t0 = *reinterpret_cast<const float4*>(tp);
    float4 t1 = *reinterpret_cast<const float4*>(tp + 4);
    __half2 h[4];
    h[0] = __floats2half2_rn(fast_tanh(s0.x + t0.x), fast_tanh(s0.y + t0.y));
    h[1] = __floats2half2_rn(fast_tanh(s0.z + t0.z), fast_tanh(s0.w + t0.w));
    h[2] = __floats2half2_rn(fast_tanh(s1.x + t1.x), fast_tanh(s1.y + t1.y));
    h[3] = __floats2half2_rn(fast_tanh(s1.z + t1.z), fast_tanh(s1.w + t1.w));
    *reinterpret_cast<uint4*>(&A_half[(size_t)m * Dd + kv]) =
        *reinterpret_cast<uint4*>(h);
}

// ---------------- Phase 1b: W -> fp16 ----------------
__global__ __launch_bounds__(256)
void prep_w_kernel(const float* __restrict__ W) {
    size_t idx = ((size_t)blockIdx.x * 256 + threadIdx.x) * 8;
    float4 w0 = *reinterpret_cast<const float4*>(W + idx);
    float4 w1 = *reinterpret_cast<const float4*>(W + idx + 4);
    __half2 h[4];
    h[0] = __floats2half2_rn(w0.x, w0.y);
    h[1] = __floats2half2_rn(w0.z, w0.w);
    h[2] = __floats2half2_rn(w1.x, w1.y);
    h[3] = __floats2half2_rn(w1.z, w1.w);
    *reinterpret_cast<uint4*>(&W_half[idx]) = *reinterpret_cast<uint4*>(h);
}

// ---------------- Phase 2: fp16 GEMM ----------------
constexpr int STAGE_H = BM * RST;                   // 5120 halfs / stage
constexpr int SMEM_TOTAL = 2 * STG * STAGE_H * 2;   // A + B = 81920 B

__global__ __launch_bounds__(256, 2)
void joiner_gemm_fp16(const float* __restrict__ bias, float* __restrict__ out) {
    extern __shared__ __half sm[];
    __half* Asm = sm;
    __half* Bsm = sm + STG * STAGE_H;

    const int tid = threadIdx.x;
    const int wid = tid >> 5, lid = tid & 31;
    const int g = lid >> 2, c = lid & 3;
    const int wm = wid >> 2, wn = wid & 3;           // warp grid 2(m) x 4(n)
    // n-block fastest (blockIdx.x) -> 8 CTAs share one A m-chunk in L2
    const size_t m0 = (size_t)blockIdx.y * BM;
    const int n0 = blockIdx.x * BN;

    // producer mapping: 2 threads per row, 16 halfs (32B) each
    const int r = tid >> 1;
    const int h = tid & 1;
    const __half* agp = A_half + (m0 + r) * Dd + h * 16;
    const __half* bgp = W_half + (size_t)(n0 + r) * Dd + h * 16;
    const uint32_t a_dst0 = smem_u32(Asm) + (uint32_t)(r * (RST * 2) + h * 32);
    const uint32_t b_dst0 = smem_u32(Bsm) + (uint32_t)(r * (RST * 2) + h * 32);

    // ldmatrix per-lane source addresses
    // A: lanes 0-15 -> rows (wm*64 + mt*16 + 0..15) @ kb; lanes 16-31 same rows @ kb+8
    const uint32_t a_lm = smem_u32(Asm)
        + (uint32_t)((wm * 64 + (lid & 15)) * (RST * 2) + ((lid >> 4) & 1) * 16);
    // B: lanes 0-7 n0..7@kb; 8-15 n0..7@kb+8; 16-23 n8..15@kb; 24-31 n8..15@kb+8
    const uint32_t b_lm = smem_u32(Bsm)
        + (uint32_t)((wn * 32 + ((lid >> 4) & 1) * 8 + (lid & 7)) * (RST * 2)
                     + ((lid >> 3) & 1) * 16);

    float acc[4][4][4];
#pragma unroll
    for (int mt = 0; mt < 4; mt++)
#pragma unroll
        for (int nt = 0; nt < 4; nt++)
#pragma unroll
            for (int i = 0; i < 4; i++) acc[mt][nt][i] = 0.0f;

#define ISSUE_STAGE(CH) do {                                                    \
        int st_ = (CH) & (STG - 1);                                             \
        const __half* ag_ = agp + (CH) * BK;                                    \
        const __half* bg_ = bgp + (CH) * BK;                                    \
        uint32_t ad_ = a_dst0 + st_ * (STAGE_H * 2);                            \
        uint32_t bd_ = b_dst0 + st_ * (STAGE_H * 2);                            \
        asm volatile(                                                           \
            "cp.async.cg.shared.global [%0], [%1], 16;\n"                       \
            "cp.async.cg.shared.global [%2], [%3], 16;\n"                       \
            "cp.async.cg.shared.global [%4], [%5], 16;\n"                       \
            "cp.async.cg.shared.global [%6], [%7], 16;\n"                       \
            "cp.async.commit_group;"                                            \
            :: "r"(ad_), "l"(ag_), "r"(ad_ + 16), "l"(ag_ + 8),                 \
               "r"(bd_), "l"(bg_), "r"(bd_ + 16), "l"(bg_ + 8) : "memory");     \
    } while (0)

    ISSUE_STAGE(0); ISSUE_STAGE(1); ISSUE_STAGE(2);

    for (int ch = 0; ch < NCH; ch++) {
        const int rem = NCH - 1 - ch;
        if (rem >= 2)      asm volatile("cp.async.wait_group 2;" ::: "memory");
        else if (rem == 1) asm volatile("cp.async.wait_group 1;" ::: "memory");
        else               asm volatile("cp.async.wait_group 0;" ::: "memory");
        __syncthreads();
        if (ch + 3 < NCH) ISSUE_STAGE(ch + 3);

        const int st = ch & (STG - 1);
        const uint32_t a_st = a_lm + st * (STAGE_H * 2);
        const uint32_t b_st = b_lm + st * (STAGE_H * 2);
#pragma unroll
        for (int ks = 0; ks < 2; ks++) {
            const int kbB = ks * 32;   // byte offset: 16 halfs
            uint32_t a[4][4];
#pragma unroll
            for (int mt = 0; mt < 4; mt++)
                ldm_x4(a[mt], a_st + mt * 16 * (RST * 2) + kbB);
            uint32_t b[2][4];
            ldm_x4(b[0], b_st + kbB);                    // nt 0,1
            ldm_x4(b[1], b_st + 16 * (RST * 2) + kbB);   // nt 2,3
#pragma unroll
            for (int nt = 0; nt < 4; nt++) {
                uint32_t b0 = b[nt >> 1][(nt & 1) * 2];
                uint32_t b1 = b[nt >> 1][(nt & 1) * 2 + 1];
#pragma unroll
                for (int mt = 0; mt < 4; mt++)
                    mma_fp16(acc[mt][nt], a[mt], b0, b1);
            }
        }
    }

    // ---- epilogue: bias + float2 stores ----
#pragma unroll
    for (int nt = 0; nt < 4; nt++) {
        const int col = n0 + wn * 32 + nt * 8 + 2 * c;
        const float2 bz = *reinterpret_cast<const float2*>(bias + col);
#pragma unroll
        for (int mt = 0; mt < 4; mt++) {
            const size_t row = m0 + wm * 64 + mt * 16 + g;
            float2 o1, o2;
            o1.x = acc[mt][nt][0] + bz.x;
            o1.y = acc[mt][nt][1] + bz.y;
            o2.x = acc[mt][nt][2] + bz.x;
            o2.y = acc[mt][nt][3] + bz.y;
            *reinterpret_cast<float2*>(out + row * Vv + col) = o1;
            *reinterpret_cast<float2*>(out + (row + 8) * Vv + col) = o2;
        }
    }
}

// Defensive tail: append lengths if harness packs the whole tuple.
__global__ void joiner_tail_kernel(const int* __restrict__ src_len,
                                   const int* __restrict__ tgt_len,
                                   float* __restrict__ out, int extras) {
    int i = threadIdx.x;
    if (i < extras) {
        size_t base = (size_t)Mm * Vv;
        if (i < Bb) out[base + i] = (float)src_len[i];
        else if (i < 2 * Bb) out[base + i] = (float)tgt_len[i - Bb];
        else out[base + i] = 0.0f;
    }
}

extern "C" void kernel_launch(void* const* d_in, const int* in_sizes, int n_in,
                              void* d_out, int out_size) {
    const float* src     = (const float*)d_in[0];
    const int*   src_len = (const int*)d_in[1];
    const float* tgt     = (const float*)d_in[2];
    const int*   tgt_len = (const int*)d_in[3];
    const float* W       = (const float*)d_in[4];
    const float* bias    = (const float*)d_in[5];
    float* out = (float*)d_out;

    prep_a_kernel<<<(unsigned)(Mm * (Dd / 8) / 256), 256>>>(src, tgt);
    prep_w_kernel<<<(Vv * Dd / 8) / 256, 256>>>(W);

    cudaFuncSetAttribute(joiner_gemm_fp16,
                         cudaFuncAttributeMaxDynamicSharedMemorySize, SMEM_TOTAL);
    dim3 grid(Vv / BN, (unsigned)(Mm / BM));   // 8 x 1250, n fastest
    joiner_gemm_fp16<<<grid, 256, SMEM_TOTAL>>>(bias, out);

    long long extras = (long long)out_size - (long long)Mm * Vv;
    if (extras > 0) {
        int e = (int)(extras > 64 ? 64 : extras);
        joiner_tail_kernel<<<1, 64>>>(src_len, tgt_len, out, e);
    }
}